// round 1
// baseline (speedup 1.0000x reference)
#include <cuda_runtime.h>
#include <cuda_bf16.h>
#include <math.h>
#include <float.h>

#define SEQ 4096
#define DMODEL 1280
#define NHEAD 20
#define HDIM 64
#define FFN 5120
#define NSEG 8
#define LN_EPS 1e-5f

// ---------------------------------------------------------------------------
// Scratch (device globals; no runtime allocation allowed)
// ---------------------------------------------------------------------------
__device__ float g_xln[SEQ * DMODEL];
__device__ float g_q[SEQ * DMODEL];
__device__ float g_k[SEQ * DMODEL];
__device__ float g_v[SEQ * DMODEL];
__device__ float g_attn[SEQ * DMODEL];
__device__ float g_h[SEQ * DMODEL];
__device__ float g_yln[SEQ * DMODEL];
__device__ float g_ffn[SEQ * FFN];

// ---------------------------------------------------------------------------
// LayerNorm: one block per row (D=1280), 256 threads
// ---------------------------------------------------------------------------
__global__ __launch_bounds__(256) void ln_kernel(const float* __restrict__ x,
                                                 const float* __restrict__ g,
                                                 const float* __restrict__ b,
                                                 float* __restrict__ out) {
    int r = blockIdx.x;
    const float* xr = x + (size_t)r * DMODEL;
    float* outr = out + (size_t)r * DMODEL;
    int tid = threadIdx.x;

    float s = 0.f, s2 = 0.f;
    for (int i = tid; i < DMODEL; i += 256) {
        float v = xr[i];
        s += v;
        s2 += v * v;
    }
    // warp reduce
    for (int off = 16; off > 0; off >>= 1) {
        s  += __shfl_xor_sync(0xffffffff, s, off);
        s2 += __shfl_xor_sync(0xffffffff, s2, off);
    }
    __shared__ float ss[8], ss2[8];
    int wid = tid >> 5, lane = tid & 31;
    if (lane == 0) { ss[wid] = s; ss2[wid] = s2; }
    __syncthreads();
    if (wid == 0) {
        s  = (lane < 8) ? ss[lane]  : 0.f;
        s2 = (lane < 8) ? ss2[lane] : 0.f;
        for (int off = 4; off > 0; off >>= 1) {
            s  += __shfl_xor_sync(0xffffffff, s, off);
            s2 += __shfl_xor_sync(0xffffffff, s2, off);
        }
        if (lane == 0) { ss[0] = s; ss2[0] = s2; }
    }
    __syncthreads();
    float mu = ss[0] * (1.0f / DMODEL);
    float var = ss2[0] * (1.0f / DMODEL) - mu * mu;
    float inv = rsqrtf(var + LN_EPS);
    for (int i = tid; i < DMODEL; i += 256) {
        outr[i] = (xr[i] - mu) * inv * g[i] + b[i];
    }
}

// ---------------------------------------------------------------------------
// Tiled SGEMM: C[M,N] = A[M,K] @ B[K,N] (+bias) (+gelu | +residual)
// BM=128 BN=128 BK=16, 256 threads, 8x8 microtile.
// EPI: 0 = bias, 1 = gelu(bias+..), 2 = bias + residual
// ---------------------------------------------------------------------------
#define EPI_BIAS 0
#define EPI_GELU 1
#define EPI_RES  2

template <int EPI>
__global__ __launch_bounds__(256) void sgemm_kernel(
    const float* __restrict__ A, const float* __restrict__ B,
    const float* __restrict__ bias, const float* __restrict__ res,
    float* __restrict__ C, int M, int N, int K) {
    __shared__ float As[16][128];
    __shared__ float Bs[16][128 + 4];

    int tid = threadIdx.x;
    int bm = blockIdx.y, bn = blockIdx.x;
    int tx = tid & 15, ty = tid >> 4;

    const float* Ab = A + (size_t)bm * 128 * K;
    const float* Bb = B + (size_t)bn * 128;

    int arow = tid >> 2;
    int acol = (tid & 3) * 4;
    int brow = tid >> 5;
    int bcol = (tid & 31) * 4;

    float acc[8][8];
#pragma unroll
    for (int i = 0; i < 8; i++)
#pragma unroll
        for (int j = 0; j < 8; j++) acc[i][j] = 0.f;

    for (int k0 = 0; k0 < K; k0 += 16) {
#pragma unroll
        for (int it = 0; it < 2; it++) {
            int r = arow + it * 64;
            float4 a = *(const float4*)(Ab + (size_t)r * K + k0 + acol);
            As[acol + 0][r] = a.x;
            As[acol + 1][r] = a.y;
            As[acol + 2][r] = a.z;
            As[acol + 3][r] = a.w;
        }
#pragma unroll
        for (int it = 0; it < 2; it++) {
            int r = brow + it * 8;
            float4 bvec = *(const float4*)(Bb + (size_t)(k0 + r) * N + bcol);
            *(float4*)&Bs[r][bcol] = bvec;
        }
        __syncthreads();
#pragma unroll
        for (int k = 0; k < 16; k++) {
            float af[8], bf[8];
#pragma unroll
            for (int i = 0; i < 8; i++) af[i] = As[k][ty * 8 + i];
#pragma unroll
            for (int j = 0; j < 8; j++) bf[j] = Bs[k][tx * 8 + j];
#pragma unroll
            for (int i = 0; i < 8; i++)
#pragma unroll
                for (int j = 0; j < 8; j++) acc[i][j] += af[i] * bf[j];
        }
        __syncthreads();
    }

#pragma unroll
    for (int i = 0; i < 8; i++) {
        int row = bm * 128 + ty * 8 + i;
#pragma unroll
        for (int j = 0; j < 8; j++) {
            int col = bn * 128 + tx * 8 + j;
            float v = acc[i][j];
            if (bias) v += bias[col];
            if (EPI == EPI_GELU) {
                v = 0.5f * v * (1.0f + erff(v * 0.70710678118654752f));
            } else if (EPI == EPI_RES) {
                v += res[(size_t)row * N + col];
            }
            C[(size_t)row * N + col] = v;
        }
    }
}

// ---------------------------------------------------------------------------
// Block-diagonal attention. grid = (SEQ/64, NHEAD). Block handles 64 query
// rows for one head; keys span the query tile's segment (<=512).
// smem: scores[64][512], Qst[64][65] (d-major), K/V chunk buffer [65*64].
// ---------------------------------------------------------------------------
#define ATT_SMEM_FLOATS (64 * 512 + 65 * 64 + 65 * 64)

__global__ __launch_bounds__(256) void attn_kernel(
    const float* __restrict__ q, const float* __restrict__ k,
    const float* __restrict__ v, const int* __restrict__ cu,
    float* __restrict__ out) {
    extern __shared__ float sm[];
    float* sc  = sm;                 // 64*512
    float* Qst = sm + 64 * 512;      // [d][i] stride 65
    float* KVb = Qst + 65 * 64;      // Kst [d][j] stride 65 / Vs [j][d] stride 64

    int h = blockIdx.y;
    int q0 = blockIdx.x * 64;

    int g = 0;
    for (int i = 0; i < NSEG; i++)
        if (cu[i] <= q0) g = i;
    int s0 = cu[g], s1 = cu[g + 1];
    int len = s1 - s0;
    if (len > 512) len = 512;
    int nchunks = (len + 63) >> 6;

    int tid = threadIdx.x;
    int tx = tid & 15, ty = tid >> 4;
    const float scale = 0.125f;  // 1/sqrt(64)

    // load Q tile transposed: Qst[d][i]
#pragma unroll
    for (int t = 0; t < 4; t++) {
        int gi = tid + t * 256;        // float4 group in [0,1024)
        int i = gi >> 4;               // row 0..63
        int d4 = (gi & 15) * 4;
        float4 qv = *(const float4*)(q + (size_t)(q0 + i) * DMODEL + h * HDIM + d4);
        Qst[(d4 + 0) * 65 + i] = qv.x;
        Qst[(d4 + 1) * 65 + i] = qv.y;
        Qst[(d4 + 2) * 65 + i] = qv.z;
        Qst[(d4 + 3) * 65 + i] = qv.w;
    }

    // ---- Phase 1: scores ----
    for (int c = 0; c < nchunks; c++) {
        __syncthreads();
#pragma unroll
        for (int t = 0; t < 4; t++) {
            int gi = tid + t * 256;
            int j = gi >> 4;
            int d4 = (gi & 15) * 4;
            int krow = s0 + c * 64 + j;
            float4 kv = make_float4(0.f, 0.f, 0.f, 0.f);
            if (krow < s1)
                kv = *(const float4*)(k + (size_t)krow * DMODEL + h * HDIM + d4);
            KVb[(d4 + 0) * 65 + j] = kv.x;
            KVb[(d4 + 1) * 65 + j] = kv.y;
            KVb[(d4 + 2) * 65 + j] = kv.z;
            KVb[(d4 + 3) * 65 + j] = kv.w;
        }
        __syncthreads();

        float cacc[4][4];
#pragma unroll
        for (int i = 0; i < 4; i++)
#pragma unroll
            for (int j = 0; j < 4; j++) cacc[i][j] = 0.f;
        int i0 = ty * 4, j0 = tx * 4;
#pragma unroll
        for (int d = 0; d < 64; d++) {
            float qa[4], kb[4];
#pragma unroll
            for (int i = 0; i < 4; i++) qa[i] = Qst[d * 65 + i0 + i];
#pragma unroll
            for (int j = 0; j < 4; j++) kb[j] = KVb[d * 65 + j0 + j];
#pragma unroll
            for (int i = 0; i < 4; i++)
#pragma unroll
                for (int j = 0; j < 4; j++) cacc[i][j] += qa[i] * kb[j];
        }
#pragma unroll
        for (int i = 0; i < 4; i++)
#pragma unroll
            for (int j = 0; j < 4; j++) {
                int jj = c * 64 + j0 + j;
                sc[(i0 + i) * 512 + jj] = (jj < len) ? cacc[i][j] * scale : 0.f;
            }
    }
    __syncthreads();

    // ---- Phase 2: softmax (8 warps, 8 rows each) ----
    int wid = tid >> 5, lane = tid & 31;
    for (int r = wid; r < 64; r += 8) {
        float* row = sc + r * 512;
        float m = -FLT_MAX;
        for (int j = lane; j < len; j += 32) m = fmaxf(m, row[j]);
        for (int off = 16; off > 0; off >>= 1)
            m = fmaxf(m, __shfl_xor_sync(0xffffffff, m, off));
        float s = 0.f;
        for (int j = lane; j < len; j += 32) {
            float e = __expf(row[j] - m);
            row[j] = e;
            s += e;
        }
        for (int off = 16; off > 0; off >>= 1)
            s += __shfl_xor_sync(0xffffffff, s, off);
        float inv = 1.0f / s;
        for (int j = lane; j < len; j += 32) row[j] *= inv;
    }

    // ---- Phase 3: O = P @ V ----
    float oacc[4][4];
#pragma unroll
    for (int i = 0; i < 4; i++)
#pragma unroll
        for (int j = 0; j < 4; j++) oacc[i][j] = 0.f;
    int i0 = ty * 4, d0 = tx * 4;

    for (int c = 0; c < nchunks; c++) {
        __syncthreads();
#pragma unroll
        for (int t = 0; t < 4; t++) {
            int gi = tid + t * 256;
            int j = gi >> 4;
            int d4 = (gi & 15) * 4;
            int vrow = s0 + c * 64 + j;
            float4 vv = make_float4(0.f, 0.f, 0.f, 0.f);
            if (vrow < s1)
                vv = *(const float4*)(v + (size_t)vrow * DMODEL + h * HDIM + d4);
            *(float4*)&KVb[j * 64 + d4] = vv;
        }
        __syncthreads();

#pragma unroll 8
        for (int j = 0; j < 64; j++) {
            float vb[4], pa[4];
#pragma unroll
            for (int l = 0; l < 4; l++) vb[l] = KVb[j * 64 + d0 + l];
#pragma unroll
            for (int i = 0; i < 4; i++) pa[i] = sc[(i0 + i) * 512 + c * 64 + j];
#pragma unroll
            for (int i = 0; i < 4; i++)
#pragma unroll
                for (int l = 0; l < 4; l++) oacc[i][l] += pa[i] * vb[l];
        }
    }

#pragma unroll
    for (int i = 0; i < 4; i++)
#pragma unroll
        for (int l = 0; l < 4; l++)
            out[(size_t)(q0 + i0 + i) * DMODEL + h * HDIM + d0 + l] = oacc[i][l];
}

// ---------------------------------------------------------------------------
// launch
// ---------------------------------------------------------------------------
extern "C" void kernel_launch(void* const* d_in, const int* in_sizes, int n_in,
                              void* d_out, int out_size) {
    const float* hidden = (const float*)d_in[0];
    const int*   cu     = (const int*)d_in[1];
    const float* Wq = (const float*)d_in[2];
    const float* bq = (const float*)d_in[3];
    const float* Wk = (const float*)d_in[4];
    const float* Wv = (const float*)d_in[5];
    const float* bv = (const float*)d_in[6];
    const float* Wo = (const float*)d_in[7];
    const float* bo = (const float*)d_in[8];
    const float* ln1_g = (const float*)d_in[9];
    const float* ln1_b = (const float*)d_in[10];
    const float* Wf1 = (const float*)d_in[11];
    const float* bf1 = (const float*)d_in[12];
    const float* Wf2 = (const float*)d_in[13];
    const float* bf2 = (const float*)d_in[14];
    const float* ln2_g = (const float*)d_in[15];
    const float* ln2_b = (const float*)d_in[16];
    float* out = (float*)d_out;

    float *xln, *qp, *kp, *vp, *attnp, *hp, *ylnp, *ffnp;
    cudaGetSymbolAddress((void**)&xln,  g_xln);
    cudaGetSymbolAddress((void**)&qp,   g_q);
    cudaGetSymbolAddress((void**)&kp,   g_k);
    cudaGetSymbolAddress((void**)&vp,   g_v);
    cudaGetSymbolAddress((void**)&attnp,g_attn);
    cudaGetSymbolAddress((void**)&hp,   g_h);
    cudaGetSymbolAddress((void**)&ylnp, g_yln);
    cudaGetSymbolAddress((void**)&ffnp, g_ffn);

    static bool attr_set = false;
    if (!attr_set) {
        cudaFuncSetAttribute(attn_kernel, cudaFuncAttributeMaxDynamicSharedMemorySize,
                             ATT_SMEM_FLOATS * (int)sizeof(float));
        attr_set = true;
    }

    dim3 blk(256);
    dim3 gemmDD(DMODEL / 128, SEQ / 128);     // N=1280
    dim3 gemmDF(FFN / 128, SEQ / 128);        // N=5120

    // LN1
    ln_kernel<<<SEQ, blk>>>(hidden, ln1_g, ln1_b, xln);
    // QKV
    sgemm_kernel<EPI_BIAS><<<gemmDD, blk>>>(xln, Wq, bq, nullptr, qp, SEQ, DMODEL, DMODEL);
    sgemm_kernel<EPI_BIAS><<<gemmDD, blk>>>(xln, Wk, nullptr, nullptr, kp, SEQ, DMODEL, DMODEL);
    sgemm_kernel<EPI_BIAS><<<gemmDD, blk>>>(xln, Wv, bv, nullptr, vp, SEQ, DMODEL, DMODEL);
    // attention
    attn_kernel<<<dim3(SEQ / 64, NHEAD), blk, ATT_SMEM_FLOATS * sizeof(float)>>>(
        qp, kp, vp, cu, attnp);
    // O proj + residual
    sgemm_kernel<EPI_RES><<<gemmDD, blk>>>(attnp, Wo, bo, hidden, hp, SEQ, DMODEL, DMODEL);
    // LN2
    ln_kernel<<<SEQ, blk>>>(hp, ln2_g, ln2_b, ylnp);
    // FFN1 + gelu
    sgemm_kernel<EPI_GELU><<<gemmDF, blk>>>(ylnp, Wf1, bf1, nullptr, ffnp, SEQ, FFN, DMODEL);
    // FFN2 + residual
    sgemm_kernel<EPI_RES><<<gemmDD, blk>>>(ffnp, Wf2, bf2, hp, out, SEQ, DMODEL, FFN);
}

// round 5
// speedup vs baseline: 2.6009x; 2.6009x over previous
#include <cuda_runtime.h>
#include <cuda_bf16.h>
#include <cstdint>
#include <math.h>
#include <float.h>

#define SEQ 4096
#define DMODEL 1280
#define NHEAD 20
#define HDIM 64
#define FFN 5120
#define NSEG 8
#define LN_EPS 1e-5f

typedef unsigned int u32;

// ---------------------------------------------------------------------------
// Scratch (device globals; no runtime allocation allowed)
// ---------------------------------------------------------------------------
__device__ float g_q[SEQ * DMODEL];
__device__ float g_k[SEQ * DMODEL];
__device__ float g_v[SEQ * DMODEL];
__device__ float g_h[SEQ * DMODEL];
__device__ float g_xln[SEQ * DMODEL];
__device__ float g_attn[SEQ * DMODEL];
__device__ float g_yln[SEQ * DMODEL];
__device__ float g_ffn[SEQ * FFN];
__device__ float g_wq[DMODEL * DMODEL];
__device__ float g_wk[DMODEL * DMODEL];
__device__ float g_wv[DMODEL * DMODEL];
__device__ float g_wo[DMODEL * DMODEL];
__device__ float g_wf1[DMODEL * FFN];
__device__ float g_wf2[FFN * DMODEL];

// ---------------------------------------------------------------------------
// tf32 round helper (round-to-nearest-even into tf32-representable fp32)
// ---------------------------------------------------------------------------
__device__ __forceinline__ float to_tf32(float x) {
    u32 r;
    asm volatile("cvt.rna.tf32.f32 %0, %1;\n" : "=r"(r) : "f"(x));
    return __uint_as_float(r);
}

// ---------------------------------------------------------------------------
// fp32 -> tf32-rounded fp32 convert (float4 granularity)
// ---------------------------------------------------------------------------
__global__ __launch_bounds__(256) void cvt_kernel(const float* __restrict__ src,
                                                  float* __restrict__ dst, int n4) {
    int i = blockIdx.x * 256 + threadIdx.x;
    if (i < n4) {
        float4 v = *(const float4*)(src + (size_t)i * 4);
        v.x = to_tf32(v.x);
        v.y = to_tf32(v.y);
        v.z = to_tf32(v.z);
        v.w = to_tf32(v.w);
        *(float4*)(dst + (size_t)i * 4) = v;
    }
}

// ---------------------------------------------------------------------------
// LayerNorm -> tf32-rounded fp32 output
// ---------------------------------------------------------------------------
__global__ __launch_bounds__(256) void ln_kernel(const float* __restrict__ x,
                                                 const float* __restrict__ gam,
                                                 const float* __restrict__ bet,
                                                 float* __restrict__ outp) {
    int r = blockIdx.x;
    const float* xr = x + (size_t)r * DMODEL;
    float* outr = outp + (size_t)r * DMODEL;
    int tid = threadIdx.x;

    float s = 0.f, s2 = 0.f;
    for (int i = tid; i < DMODEL; i += 256) {
        float v = xr[i];
        s += v;
        s2 += v * v;
    }
    for (int off = 16; off > 0; off >>= 1) {
        s  += __shfl_xor_sync(0xffffffff, s, off);
        s2 += __shfl_xor_sync(0xffffffff, s2, off);
    }
    __shared__ float ss[8];
    __shared__ float ss2[8];
    int wid = tid >> 5;
    int lane = tid & 31;
    if (lane == 0) { ss[wid] = s; ss2[wid] = s2; }
    __syncthreads();
    if (wid == 0) {
        s  = (lane < 8) ? ss[lane]  : 0.f;
        s2 = (lane < 8) ? ss2[lane] : 0.f;
        for (int off = 4; off > 0; off >>= 1) {
            s  += __shfl_xor_sync(0xffffffff, s, off);
            s2 += __shfl_xor_sync(0xffffffff, s2, off);
        }
        if (lane == 0) { ss[0] = s; ss2[0] = s2; }
    }
    __syncthreads();
    float mu = ss[0] * (1.0f / DMODEL);
    float var = ss2[0] * (1.0f / DMODEL) - mu * mu;
    float inv = rsqrtf(var + LN_EPS);
    for (int i = tid; i < DMODEL; i += 256) {
        float v = (xr[i] - mu) * inv * gam[i] + bet[i];
        outr[i] = to_tf32(v);
    }
}

// ---------------------------------------------------------------------------
// tf32 tensor-core GEMM: C[M,N] = A[M,K] @ B[K,N] (+bias)(+gelu|+res)
// BM=128 BN=128 BK=16, 8 warps (4x2), warp tile 32x64, m16n8k8 tf32 mma.
// A/B must be pre-rounded to tf32 precision.
// ---------------------------------------------------------------------------
#define EPI_BIAS 0
#define EPI_GELU 1
#define EPI_RES  2

#define APITCH 20
#define BPITCH 136

__device__ __forceinline__ void mma_tf32(float* c, u32 a0, u32 a1, u32 a2, u32 a3,
                                         u32 b0, u32 b1) {
    asm volatile(
        "mma.sync.aligned.m16n8k8.row.col.f32.tf32.tf32.f32 "
        "{%0,%1,%2,%3},{%4,%5,%6,%7},{%8,%9},{%0,%1,%2,%3};\n"
        : "+f"(c[0]), "+f"(c[1]), "+f"(c[2]), "+f"(c[3])
        : "r"(a0), "r"(a1), "r"(a2), "r"(a3), "r"(b0), "r"(b1));
}
__device__ __forceinline__ void cp_async16(u32 dst, const void* src) {
    asm volatile("cp.async.cg.shared.global [%0],[%1],16;\n" :: "r"(dst), "l"(src));
}
__device__ __forceinline__ void cp_commit() {
    asm volatile("cp.async.commit_group;\n");
}
__device__ __forceinline__ void cp_wait1() {
    asm volatile("cp.async.wait_group 1;\n");
}
__device__ __forceinline__ void cp_wait0() {
    asm volatile("cp.async.wait_group 0;\n");
}

// tile loader: load A[128x16] and B[16x128] fp32 tiles into stage smem
__device__ __forceinline__ void sg_load_tile(
    const float* A, const float* B, float* As_s, float* Bs_s,
    int k0, int bm, int bn, int K, int N,
    int a_ld_row, int a_ld_col, int b_ld_row, int b_ld_col) {
    u32 d0 = (u32)__cvta_generic_to_shared(As_s + a_ld_row * APITCH + a_ld_col);
    cp_async16(d0, A + (size_t)(bm * 128 + a_ld_row) * K + k0 + a_ld_col);
    u32 d1 = (u32)__cvta_generic_to_shared(As_s + (a_ld_row + 64) * APITCH + a_ld_col);
    cp_async16(d1, A + (size_t)(bm * 128 + a_ld_row + 64) * K + k0 + a_ld_col);
    u32 d2 = (u32)__cvta_generic_to_shared(Bs_s + b_ld_row * BPITCH + b_ld_col);
    cp_async16(d2, B + (size_t)(k0 + b_ld_row) * N + bn * 128 + b_ld_col);
    u32 d3 = (u32)__cvta_generic_to_shared(Bs_s + (b_ld_row + 8) * BPITCH + b_ld_col);
    cp_async16(d3, B + (size_t)(k0 + b_ld_row + 8) * N + bn * 128 + b_ld_col);
}

template <int EPI, int OUTRND>
__global__ __launch_bounds__(256) void tgemm_kernel(
    const float* __restrict__ A, const float* __restrict__ B,
    const float* __restrict__ bias, const float* __restrict__ res,
    float* __restrict__ C, int M, int N, int K) {
    __shared__ float As[2 * 128 * APITCH];
    __shared__ float Bs[2 * 16 * BPITCH];

    int tid = threadIdx.x;
    int bm = blockIdx.y;
    int bn = blockIdx.x;
    int lane = tid & 31;
    int warp = tid >> 5;
    int wm = warp >> 1;
    int wn = warp & 1;

    int a_ld_row = tid >> 2;        // 0..63
    int a_ld_col = (tid & 3) * 4;   // 0,4,8,12
    int b_ld_row = tid >> 5;        // 0..7
    int b_ld_col = (tid & 31) * 4;  // 0..124

    float acc[2][8][4];
#pragma unroll
    for (int mi = 0; mi < 2; mi++) {
#pragma unroll
        for (int nj = 0; nj < 8; nj++) {
#pragma unroll
            for (int e = 0; e < 4; e++) acc[mi][nj][e] = 0.f;
        }
    }

    int KT = K / 16;

    sg_load_tile(A, B, As, Bs, 0, bm, bn, K, N,
                 a_ld_row, a_ld_col, b_ld_row, b_ld_col);
    cp_commit();

    int gID = lane >> 2;   // 0..7
    int tig = lane & 3;    // 0..3

    for (int kt = 0; kt < KT; kt++) {
        int s = kt & 1;
        if (kt + 1 < KT) {
            int s2 = s ^ 1;
            sg_load_tile(A, B, As + s2 * 128 * APITCH, Bs + s2 * 16 * BPITCH,
                         (kt + 1) * 16, bm, bn, K, N,
                         a_ld_row, a_ld_col, b_ld_row, b_ld_col);
            cp_commit();
            cp_wait1();
        } else {
            cp_wait0();
        }
        __syncthreads();

        float* As_s = As + s * 128 * APITCH;
        float* Bs_s = Bs + s * 16 * BPITCH;

#pragma unroll
        for (int kk = 0; kk < 2; kk++) {
            int k0 = kk * 8;
            u32 a_frag[2][4];
#pragma unroll
            for (int mi = 0; mi < 2; mi++) {
                int r0 = wm * 32 + mi * 16;
                a_frag[mi][0] = __float_as_uint(As_s[(r0 + gID) * APITCH + k0 + tig]);
                a_frag[mi][1] = __float_as_uint(As_s[(r0 + 8 + gID) * APITCH + k0 + tig]);
                a_frag[mi][2] = __float_as_uint(As_s[(r0 + gID) * APITCH + k0 + 4 + tig]);
                a_frag[mi][3] = __float_as_uint(As_s[(r0 + 8 + gID) * APITCH + k0 + 4 + tig]);
            }
#pragma unroll
            for (int nj = 0; nj < 8; nj++) {
                int n0 = wn * 64 + nj * 8;
                u32 b0 = __float_as_uint(Bs_s[(k0 + tig) * BPITCH + n0 + gID]);
                u32 b1 = __float_as_uint(Bs_s[(k0 + 4 + tig) * BPITCH + n0 + gID]);
#pragma unroll
                for (int mi = 0; mi < 2; mi++) {
                    mma_tf32(acc[mi][nj], a_frag[mi][0], a_frag[mi][1],
                             a_frag[mi][2], a_frag[mi][3], b0, b1);
                }
            }
        }
        __syncthreads();
    }

    // ---- epilogue ----
#pragma unroll
    for (int mi = 0; mi < 2; mi++) {
        int row0 = bm * 128 + wm * 32 + mi * 16 + gID;
#pragma unroll
        for (int nj = 0; nj < 8; nj++) {
            int col = bn * 128 + wn * 64 + nj * 8 + tig * 2;
            float v0 = acc[mi][nj][0];
            float v1 = acc[mi][nj][1];
            float v2 = acc[mi][nj][2];
            float v3 = acc[mi][nj][3];
            if (bias != 0) {
                float b0 = bias[col];
                float b1 = bias[col + 1];
                v0 += b0; v1 += b1; v2 += b0; v3 += b1;
            }
            if (EPI == EPI_GELU) {
                v0 = 0.5f * v0 * (1.0f + erff(v0 * 0.70710678118654752f));
                v1 = 0.5f * v1 * (1.0f + erff(v1 * 0.70710678118654752f));
                v2 = 0.5f * v2 * (1.0f + erff(v2 * 0.70710678118654752f));
                v3 = 0.5f * v3 * (1.0f + erff(v3 * 0.70710678118654752f));
            }
            if (EPI == EPI_RES) {
                v0 += res[(size_t)row0 * N + col];
                v1 += res[(size_t)row0 * N + col + 1];
                v2 += res[(size_t)(row0 + 8) * N + col];
                v3 += res[(size_t)(row0 + 8) * N + col + 1];
            }
            if (OUTRND) {
                v0 = to_tf32(v0);
                v1 = to_tf32(v1);
                v2 = to_tf32(v2);
                v3 = to_tf32(v3);
            }
            C[(size_t)row0 * N + col] = v0;
            C[(size_t)row0 * N + col + 1] = v1;
            C[(size_t)(row0 + 8) * N + col] = v2;
            C[(size_t)(row0 + 8) * N + col + 1] = v3;
        }
    }
}

// ---------------------------------------------------------------------------
// Block-diagonal attention (fp32 compute, tf32-rounded fp32 output)
// ---------------------------------------------------------------------------
#define ATT_SMEM_FLOATS (64 * 512 + 65 * 64 + 65 * 64)

__global__ __launch_bounds__(256) void attn_kernel(
    const float* __restrict__ q, const float* __restrict__ k,
    const float* __restrict__ v, const int* __restrict__ cu,
    float* __restrict__ outp) {
    extern __shared__ float sm[];
    float* sc  = sm;
    float* Qst = sm + 64 * 512;
    float* KVb = Qst + 65 * 64;

    int h = blockIdx.y;
    int q0 = blockIdx.x * 64;

    int g = 0;
    for (int i = 0; i < NSEG; i++) {
        if (cu[i] <= q0) g = i;
    }
    int s0 = cu[g];
    int s1 = cu[g + 1];
    int len = s1 - s0;
    if (len > 512) len = 512;
    int nchunks = (len + 63) >> 6;

    int tid = threadIdx.x;
    int tx = tid & 15;
    int ty = tid >> 4;
    const float scale = 0.125f;

#pragma unroll
    for (int t = 0; t < 4; t++) {
        int gi = tid + t * 256;
        int i = gi >> 4;
        int d4 = (gi & 15) * 4;
        float4 qv = *(const float4*)(q + (size_t)(q0 + i) * DMODEL + h * HDIM + d4);
        Qst[(d4 + 0) * 65 + i] = qv.x;
        Qst[(d4 + 1) * 65 + i] = qv.y;
        Qst[(d4 + 2) * 65 + i] = qv.z;
        Qst[(d4 + 3) * 65 + i] = qv.w;
    }

    for (int c = 0; c < nchunks; c++) {
        __syncthreads();
#pragma unroll
        for (int t = 0; t < 4; t++) {
            int gi = tid + t * 256;
            int j = gi >> 4;
            int d4 = (gi & 15) * 4;
            int krow = s0 + c * 64 + j;
            float4 kv = make_float4(0.f, 0.f, 0.f, 0.f);
            if (krow < s1) {
                kv = *(const float4*)(k + (size_t)krow * DMODEL + h * HDIM + d4);
            }
            KVb[(d4 + 0) * 65 + j] = kv.x;
            KVb[(d4 + 1) * 65 + j] = kv.y;
            KVb[(d4 + 2) * 65 + j] = kv.z;
            KVb[(d4 + 3) * 65 + j] = kv.w;
        }
        __syncthreads();

        float cacc[4][4];
#pragma unroll
        for (int i = 0; i < 4; i++) {
#pragma unroll
            for (int j = 0; j < 4; j++) cacc[i][j] = 0.f;
        }
        int i0 = ty * 4;
        int j0 = tx * 4;
#pragma unroll
        for (int d = 0; d < 64; d++) {
            float qa[4];
            float kb[4];
#pragma unroll
            for (int i = 0; i < 4; i++) qa[i] = Qst[d * 65 + i0 + i];
#pragma unroll
            for (int j = 0; j < 4; j++) kb[j] = KVb[d * 65 + j0 + j];
#pragma unroll
            for (int i = 0; i < 4; i++) {
#pragma unroll
                for (int j = 0; j < 4; j++) cacc[i][j] += qa[i] * kb[j];
            }
        }
#pragma unroll
        for (int i = 0; i < 4; i++) {
#pragma unroll
            for (int j = 0; j < 4; j++) {
                int jj = c * 64 + j0 + j;
                sc[(i0 + i) * 512 + jj] = (jj < len) ? cacc[i][j] * scale : 0.f;
            }
        }
    }
    __syncthreads();

    int wid = tid >> 5;
    int lane = tid & 31;
    for (int r = wid; r < 64; r += 8) {
        float* row = sc + r * 512;
        float m = -FLT_MAX;
        for (int j = lane; j < len; j += 32) m = fmaxf(m, row[j]);
        for (int off = 16; off > 0; off >>= 1) {
            m = fmaxf(m, __shfl_xor_sync(0xffffffff, m, off));
        }
        float s = 0.f;
        for (int j = lane; j < len; j += 32) {
            float e = __expf(row[j] - m);
            row[j] = e;
            s += e;
        }
        for (int off = 16; off > 0; off >>= 1) {
            s += __shfl_xor_sync(0xffffffff, s, off);
        }
        float inv = 1.0f / s;
        for (int j = lane; j < len; j += 32) row[j] *= inv;
    }

    float oacc[4][4];
#pragma unroll
    for (int i = 0; i < 4; i++) {
#pragma unroll
        for (int j = 0; j < 4; j++) oacc[i][j] = 0.f;
    }
    int i0 = ty * 4;
    int d0 = tx * 4;

    for (int c = 0; c < nchunks; c++) {
        __syncthreads();
#pragma unroll
        for (int t = 0; t < 4; t++) {
            int gi = tid + t * 256;
            int j = gi >> 4;
            int d4 = (gi & 15) * 4;
            int vrow = s0 + c * 64 + j;
            float4 vv = make_float4(0.f, 0.f, 0.f, 0.f);
            if (vrow < s1) {
                vv = *(const float4*)(v + (size_t)vrow * DMODEL + h * HDIM + d4);
            }
            *(float4*)(KVb + j * 64 + d4) = vv;
        }
        __syncthreads();

#pragma unroll 8
        for (int j = 0; j < 64; j++) {
            float vb[4];
            float pa[4];
#pragma unroll
            for (int l = 0; l < 4; l++) vb[l] = KVb[j * 64 + d0 + l];
#pragma unroll
            for (int i = 0; i < 4; i++) pa[i] = sc[(i0 + i) * 512 + c * 64 + j];
#pragma unroll
            for (int i = 0; i < 4; i++) {
#pragma unroll
                for (int l = 0; l < 4; l++) oacc[i][l] += pa[i] * vb[l];
            }
        }
    }

#pragma unroll
    for (int i = 0; i < 4; i++) {
        float* op = outp + (size_t)(q0 + i0 + i) * DMODEL + h * HDIM + d0;
        op[0] = to_tf32(oacc[i][0]);
        op[1] = to_tf32(oacc[i][1]);
        op[2] = to_tf32(oacc[i][2]);
        op[3] = to_tf32(oacc[i][3]);
    }
}

// ---------------------------------------------------------------------------
// launch
// ---------------------------------------------------------------------------
extern "C" void kernel_launch(void* const* d_in, const int* in_sizes, int n_in,
                              void* d_out, int out_size) {
    const float* hidden = (const float*)d_in[0];
    const int*   cu     = (const int*)d_in[1];
    const float* Wq = (const float*)d_in[2];
    const float* bq = (const float*)d_in[3];
    const float* Wk = (const float*)d_in[4];
    const float* Wv = (const float*)d_in[5];
    const float* bv = (const float*)d_in[6];
    const float* Wo = (const float*)d_in[7];
    const float* bo = (const float*)d_in[8];
    const float* ln1_g = (const float*)d_in[9];
    const float* ln1_b = (const float*)d_in[10];
    const float* Wf1 = (const float*)d_in[11];
    const float* bf1 = (const float*)d_in[12];
    const float* Wf2 = (const float*)d_in[13];
    const float* bf2 = (const float*)d_in[14];
    const float* ln2_g = (const float*)d_in[15];
    const float* ln2_b = (const float*)d_in[16];
    float* out = (float*)d_out;

    float *qp, *kp, *vp, *hp, *xlnp, *attnp, *ylnp, *ffnp;
    float *wqp, *wkp, *wvp, *wop, *wf1p, *wf2p;
    cudaGetSymbolAddress((void**)&qp,   g_q);
    cudaGetSymbolAddress((void**)&kp,   g_k);
    cudaGetSymbolAddress((void**)&vp,   g_v);
    cudaGetSymbolAddress((void**)&hp,   g_h);
    cudaGetSymbolAddress((void**)&xlnp, g_xln);
    cudaGetSymbolAddress((void**)&attnp,g_attn);
    cudaGetSymbolAddress((void**)&ylnp, g_yln);
    cudaGetSymbolAddress((void**)&ffnp, g_ffn);
    cudaGetSymbolAddress((void**)&wqp,  g_wq);
    cudaGetSymbolAddress((void**)&wkp,  g_wk);
    cudaGetSymbolAddress((void**)&wvp,  g_wv);
    cudaGetSymbolAddress((void**)&wop,  g_wo);
    cudaGetSymbolAddress((void**)&wf1p, g_wf1);
    cudaGetSymbolAddress((void**)&wf2p, g_wf2);

    static bool attr_set = false;
    if (!attr_set) {
        cudaFuncSetAttribute(attn_kernel, cudaFuncAttributeMaxDynamicSharedMemorySize,
                             ATT_SMEM_FLOATS * (int)sizeof(float));
        attr_set = true;
    }

    dim3 blk(256);
    int nDD4 = DMODEL * DMODEL / 4;
    int nDF4 = DMODEL * FFN / 4;
    cvt_kernel<<<(nDD4 + 255) / 256, blk>>>(Wq,  wqp,  nDD4);
    cvt_kernel<<<(nDD4 + 255) / 256, blk>>>(Wk,  wkp,  nDD4);
    cvt_kernel<<<(nDD4 + 255) / 256, blk>>>(Wv,  wvp,  nDD4);
    cvt_kernel<<<(nDD4 + 255) / 256, blk>>>(Wo,  wop,  nDD4);
    cvt_kernel<<<(nDF4 + 255) / 256, blk>>>(Wf1, wf1p, nDF4);
    cvt_kernel<<<(nDF4 + 255) / 256, blk>>>(Wf2, wf2p, nDF4);

    dim3 gemmDD(DMODEL / 128, SEQ / 128);
    dim3 gemmDF(FFN / 128, SEQ / 128);

    ln_kernel<<<SEQ, blk>>>(hidden, ln1_g, ln1_b, xlnp);
    tgemm_kernel<EPI_BIAS, 0><<<gemmDD, blk>>>(xlnp, wqp, bq, 0, qp, SEQ, DMODEL, DMODEL);
    tgemm_kernel<EPI_BIAS, 0><<<gemmDD, blk>>>(xlnp, wkp, 0, 0, kp, SEQ, DMODEL, DMODEL);
    tgemm_kernel<EPI_BIAS, 0><<<gemmDD, blk>>>(xlnp, wvp, bv, 0, vp, SEQ, DMODEL, DMODEL);
    attn_kernel<<<dim3(SEQ / 64, NHEAD), blk, ATT_SMEM_FLOATS * sizeof(float)>>>(
        qp, kp, vp, cu, attnp);
    tgemm_kernel<EPI_RES, 0><<<gemmDD, blk>>>(attnp, wop, bo, hidden, hp,
                                              SEQ, DMODEL, DMODEL);
    ln_kernel<<<SEQ, blk>>>(hp, ln2_g, ln2_b, ylnp);
    tgemm_kernel<EPI_GELU, 1><<<gemmDF, blk>>>(ylnp, wf1p, bf1, 0, ffnp,
                                               SEQ, FFN, DMODEL);
    tgemm_kernel<EPI_RES, 0><<<gemmDD, blk>>>(ffnp, wf2p, bf2, hp, out,
                                              SEQ, DMODEL, FFN);
}

// round 6
// speedup vs baseline: 2.9290x; 1.1262x over previous
#include <cuda_runtime.h>
#include <cuda_bf16.h>
#include <cstdint>
#include <math.h>
#include <float.h>

#define SEQ 4096
#define DMODEL 1280
#define NHEAD 20
#define HDIM 64
#define FFN 5120
#define NSEG 8
#define LN_EPS 1e-5f

typedef unsigned int u32;

// ---------------------------------------------------------------------------
// Scratch (device globals; no runtime allocation allowed)
// ---------------------------------------------------------------------------
__device__ float g_q[SEQ * DMODEL];
__device__ float g_k[SEQ * DMODEL];
__device__ float g_v[SEQ * DMODEL];
__device__ float g_h[SEQ * DMODEL];
__device__ float g_xln[SEQ * DMODEL];
__device__ float g_attn[SEQ * DMODEL];
__device__ float g_yln[SEQ * DMODEL];
__device__ float g_ffn[SEQ * FFN];
__device__ float g_wq[DMODEL * DMODEL];
__device__ float g_wk[DMODEL * DMODEL];
__device__ float g_wv[DMODEL * DMODEL];
__device__ float g_wo[DMODEL * DMODEL];
__device__ float g_wf1[DMODEL * FFN];
__device__ float g_wf2[FFN * DMODEL];

// ---------------------------------------------------------------------------
// tf32 round helper (round-to-nearest into tf32-representable fp32)
// ---------------------------------------------------------------------------
__device__ __forceinline__ float to_tf32(float x) {
    u32 r;
    asm volatile("cvt.rna.tf32.f32 %0, %1;\n" : "=r"(r) : "f"(x));
    return __uint_as_float(r);
}

// ---------------------------------------------------------------------------
// fp32 -> tf32-rounded fp32 convert (float4 granularity)
// ---------------------------------------------------------------------------
__global__ __launch_bounds__(256) void cvt_kernel(const float* __restrict__ src,
                                                  float* __restrict__ dst, int n4) {
    int i = blockIdx.x * 256 + threadIdx.x;
    if (i < n4) {
        float4 v = *(const float4*)(src + (size_t)i * 4);
        v.x = to_tf32(v.x);
        v.y = to_tf32(v.y);
        v.z = to_tf32(v.z);
        v.w = to_tf32(v.w);
        *(float4*)(dst + (size_t)i * 4) = v;
    }
}

// ---------------------------------------------------------------------------
// LayerNorm -> tf32-rounded fp32 output
// ---------------------------------------------------------------------------
__global__ __launch_bounds__(256) void ln_kernel(const float* __restrict__ x,
                                                 const float* __restrict__ gam,
                                                 const float* __restrict__ bet,
                                                 float* __restrict__ outp) {
    int r = blockIdx.x;
    const float* xr = x + (size_t)r * DMODEL;
    float* outr = outp + (size_t)r * DMODEL;
    int tid = threadIdx.x;

    float s = 0.f, s2 = 0.f;
    for (int i = tid; i < DMODEL; i += 256) {
        float v = xr[i];
        s += v;
        s2 += v * v;
    }
    for (int off = 16; off > 0; off >>= 1) {
        s  += __shfl_xor_sync(0xffffffff, s, off);
        s2 += __shfl_xor_sync(0xffffffff, s2, off);
    }
    __shared__ float ss[8];
    __shared__ float ss2[8];
    int wid = tid >> 5;
    int lane = tid & 31;
    if (lane == 0) { ss[wid] = s; ss2[wid] = s2; }
    __syncthreads();
    if (wid == 0) {
        s  = (lane < 8) ? ss[lane]  : 0.f;
        s2 = (lane < 8) ? ss2[lane] : 0.f;
        for (int off = 4; off > 0; off >>= 1) {
            s  += __shfl_xor_sync(0xffffffff, s, off);
            s2 += __shfl_xor_sync(0xffffffff, s2, off);
        }
        if (lane == 0) { ss[0] = s; ss2[0] = s2; }
    }
    __syncthreads();
    float mu = ss[0] * (1.0f / DMODEL);
    float var = ss2[0] * (1.0f / DMODEL) - mu * mu;
    float inv = rsqrtf(var + LN_EPS);
    for (int i = tid; i < DMODEL; i += 256) {
        float v = (xr[i] - mu) * inv * gam[i] + bet[i];
        outr[i] = to_tf32(v);
    }
}

// ---------------------------------------------------------------------------
// tf32 tensor-core GEMM: C[M,N] = A[M,K] @ B[K,N] (+bias)(+gelu|+res)
// BM=128 BN=128 BK=16, 8 warps (4x2), warp tile 32x64, m16n8k8 tf32 mma.
// ---------------------------------------------------------------------------
#define EPI_BIAS 0
#define EPI_GELU 1
#define EPI_RES  2

#define APITCH 20
#define BPITCH 136

__device__ __forceinline__ void mma_tf32(float* c, u32 a0, u32 a1, u32 a2, u32 a3,
                                         u32 b0, u32 b1) {
    asm volatile(
        "mma.sync.aligned.m16n8k8.row.col.f32.tf32.tf32.f32 "
        "{%0,%1,%2,%3},{%4,%5,%6,%7},{%8,%9},{%0,%1,%2,%3};\n"
        : "+f"(c[0]), "+f"(c[1]), "+f"(c[2]), "+f"(c[3])
        : "r"(a0), "r"(a1), "r"(a2), "r"(a3), "r"(b0), "r"(b1));
}
__device__ __forceinline__ void cp_async16(u32 dst, const void* src) {
    asm volatile("cp.async.cg.shared.global [%0],[%1],16;\n" :: "r"(dst), "l"(src));
}
__device__ __forceinline__ void cp_commit() {
    asm volatile("cp.async.commit_group;\n");
}
__device__ __forceinline__ void cp_wait1() {
    asm volatile("cp.async.wait_group 1;\n");
}
__device__ __forceinline__ void cp_wait0() {
    asm volatile("cp.async.wait_group 0;\n");
}

__device__ __forceinline__ void sg_load_tile(
    const float* A, const float* B, float* As_s, float* Bs_s,
    int k0, int bm, int bn, int K, int N,
    int a_ld_row, int a_ld_col, int b_ld_row, int b_ld_col) {
    u32 d0 = (u32)__cvta_generic_to_shared(As_s + a_ld_row * APITCH + a_ld_col);
    cp_async16(d0, A + (size_t)(bm * 128 + a_ld_row) * K + k0 + a_ld_col);
    u32 d1 = (u32)__cvta_generic_to_shared(As_s + (a_ld_row + 64) * APITCH + a_ld_col);
    cp_async16(d1, A + (size_t)(bm * 128 + a_ld_row + 64) * K + k0 + a_ld_col);
    u32 d2 = (u32)__cvta_generic_to_shared(Bs_s + b_ld_row * BPITCH + b_ld_col);
    cp_async16(d2, B + (size_t)(k0 + b_ld_row) * N + bn * 128 + b_ld_col);
    u32 d3 = (u32)__cvta_generic_to_shared(Bs_s + (b_ld_row + 8) * BPITCH + b_ld_col);
    cp_async16(d3, B + (size_t)(k0 + b_ld_row + 8) * N + bn * 128 + b_ld_col);
}

template <int EPI, int OUTRND>
__global__ __launch_bounds__(256) void tgemm_kernel(
    const float* __restrict__ A, const float* __restrict__ B,
    const float* __restrict__ bias, const float* __restrict__ res,
    float* __restrict__ C, int M, int N, int K) {
    __shared__ float As[2 * 128 * APITCH];
    __shared__ float Bs[2 * 16 * BPITCH];

    int tid = threadIdx.x;
    int bm = blockIdx.y;
    int bn = blockIdx.x;
    int lane = tid & 31;
    int warp = tid >> 5;
    int wm = warp >> 1;
    int wn = warp & 1;

    int a_ld_row = tid >> 2;
    int a_ld_col = (tid & 3) * 4;
    int b_ld_row = tid >> 5;
    int b_ld_col = (tid & 31) * 4;

    float acc[2][8][4];
#pragma unroll
    for (int mi = 0; mi < 2; mi++) {
#pragma unroll
        for (int nj = 0; nj < 8; nj++) {
#pragma unroll
            for (int e = 0; e < 4; e++) acc[mi][nj][e] = 0.f;
        }
    }

    int KT = K / 16;

    sg_load_tile(A, B, As, Bs, 0, bm, bn, K, N,
                 a_ld_row, a_ld_col, b_ld_row, b_ld_col);
    cp_commit();

    int gID = lane >> 2;
    int tig = lane & 3;

    for (int kt = 0; kt < KT; kt++) {
        int s = kt & 1;
        if (kt + 1 < KT) {
            int s2 = s ^ 1;
            sg_load_tile(A, B, As + s2 * 128 * APITCH, Bs + s2 * 16 * BPITCH,
                         (kt + 1) * 16, bm, bn, K, N,
                         a_ld_row, a_ld_col, b_ld_row, b_ld_col);
            cp_commit();
            cp_wait1();
        } else {
            cp_wait0();
        }
        __syncthreads();

        float* As_s = As + s * 128 * APITCH;
        float* Bs_s = Bs + s * 16 * BPITCH;

#pragma unroll
        for (int kk = 0; kk < 2; kk++) {
            int k0 = kk * 8;
            u32 a_frag[2][4];
#pragma unroll
            for (int mi = 0; mi < 2; mi++) {
                int r0 = wm * 32 + mi * 16;
                a_frag[mi][0] = __float_as_uint(As_s[(r0 + gID) * APITCH + k0 + tig]);
                a_frag[mi][1] = __float_as_uint(As_s[(r0 + 8 + gID) * APITCH + k0 + tig]);
                a_frag[mi][2] = __float_as_uint(As_s[(r0 + gID) * APITCH + k0 + 4 + tig]);
                a_frag[mi][3] = __float_as_uint(As_s[(r0 + 8 + gID) * APITCH + k0 + 4 + tig]);
            }
#pragma unroll
            for (int nj = 0; nj < 8; nj++) {
                int n0 = wn * 64 + nj * 8;
                u32 b0 = __float_as_uint(Bs_s[(k0 + tig) * BPITCH + n0 + gID]);
                u32 b1 = __float_as_uint(Bs_s[(k0 + 4 + tig) * BPITCH + n0 + gID]);
#pragma unroll
                for (int mi = 0; mi < 2; mi++) {
                    mma_tf32(acc[mi][nj], a_frag[mi][0], a_frag[mi][1],
                             a_frag[mi][2], a_frag[mi][3], b0, b1);
                }
            }
        }
        __syncthreads();
    }

#pragma unroll
    for (int mi = 0; mi < 2; mi++) {
        int row0 = bm * 128 + wm * 32 + mi * 16 + gID;
#pragma unroll
        for (int nj = 0; nj < 8; nj++) {
            int col = bn * 128 + wn * 64 + nj * 8 + tig * 2;
            float v0 = acc[mi][nj][0];
            float v1 = acc[mi][nj][1];
            float v2 = acc[mi][nj][2];
            float v3 = acc[mi][nj][3];
            if (bias != 0) {
                float b0 = bias[col];
                float b1 = bias[col + 1];
                v0 += b0; v1 += b1; v2 += b0; v3 += b1;
            }
            if (EPI == EPI_GELU) {
                v0 = 0.5f * v0 * (1.0f + erff(v0 * 0.70710678118654752f));
                v1 = 0.5f * v1 * (1.0f + erff(v1 * 0.70710678118654752f));
                v2 = 0.5f * v2 * (1.0f + erff(v2 * 0.70710678118654752f));
                v3 = 0.5f * v3 * (1.0f + erff(v3 * 0.70710678118654752f));
            }
            if (EPI == EPI_RES) {
                v0 += res[(size_t)row0 * N + col];
                v1 += res[(size_t)row0 * N + col + 1];
                v2 += res[(size_t)(row0 + 8) * N + col];
                v3 += res[(size_t)(row0 + 8) * N + col + 1];
            }
            if (OUTRND) {
                v0 = to_tf32(v0);
                v1 = to_tf32(v1);
                v2 = to_tf32(v2);
                v3 = to_tf32(v3);
            }
            C[(size_t)row0 * N + col] = v0;
            C[(size_t)row0 * N + col + 1] = v1;
            C[(size_t)(row0 + 8) * N + col] = v2;
            C[(size_t)(row0 + 8) * N + col + 1] = v3;
        }
    }
}

// ---------------------------------------------------------------------------
// Block-diagonal attention, tensor-core tf32 version.
// Block = 64 queries x 1 head. Warps 4x2: wm = 16-row m-tile, wn = 32-col half.
// Phase1: S = Q K^T via mma (K chunk transposed in smem, pitch 73).
// Phase2: fp32 softmax over len keys, P rounded to tf32 in place.
// Phase3: O = P V via mma (V natural layout, pitch 72).
// q/k/v must be tf32-pre-rounded fp32.
// ---------------------------------------------------------------------------
#define SPITCH 516
#define QPITCH 68
#define KVPITCH_K 73
#define KVPITCH_V 72
#define ATT_SMEM_FLOATS (64 * SPITCH + 64 * QPITCH + 64 * KVPITCH_K)

__global__ __launch_bounds__(256) void attn_kernel(
    const float* __restrict__ q, const float* __restrict__ k,
    const float* __restrict__ v, const int* __restrict__ cu,
    float* __restrict__ outp) {
    extern __shared__ float sm[];
    float* sc  = sm;                       // 64 x SPITCH scores
    float* Qs  = sm + 64 * SPITCH;         // 64 x QPITCH, natural [i][d]
    float* KVs = Qs + 64 * QPITCH;         // K: [d][j] pitch 73 / V: [j][d] pitch 72

    int h = blockIdx.y;
    int q0 = blockIdx.x * 64;

    int g = 0;
    for (int i = 0; i < NSEG; i++) {
        if (cu[i] <= q0) g = i;
    }
    int s0 = cu[g];
    int s1 = cu[g + 1];
    int len = s1 - s0;
    if (len > 512) len = 512;
    int nchunks = (len + 63) >> 6;

    int tid = threadIdx.x;
    int lane = tid & 31;
    int warp = tid >> 5;
    int wm = warp >> 1;      // 0..3 -> 16-row m tile
    int wn = warp & 1;       // 0..1 -> 32-col half
    int gID = lane >> 2;     // 0..7
    int tig = lane & 3;      // 0..3
    const float scale = 0.125f;

    // ---- load Q tile natural [i][d] ----
#pragma unroll
    for (int t = 0; t < 4; t++) {
        int gi = tid + t * 256;
        int i = gi >> 4;
        int d4 = (gi & 15) * 4;
        float4 qv = *(const float4*)(q + (size_t)(q0 + i) * DMODEL + h * HDIM + d4);
        *(float4*)(Qs + i * QPITCH + d4) = qv;
    }
    __syncthreads();

    // ---- Q A-fragments (m16 x k64 per warp) ----
    int m0 = wm * 16;
    u32 qa[8][4];
#pragma unroll
    for (int ks = 0; ks < 8; ks++) {
        int k0 = ks * 8;
        qa[ks][0] = __float_as_uint(Qs[(m0 + gID) * QPITCH + k0 + tig]);
        qa[ks][1] = __float_as_uint(Qs[(m0 + 8 + gID) * QPITCH + k0 + tig]);
        qa[ks][2] = __float_as_uint(Qs[(m0 + gID) * QPITCH + k0 + 4 + tig]);
        qa[ks][3] = __float_as_uint(Qs[(m0 + 8 + gID) * QPITCH + k0 + 4 + tig]);
    }

    // ---- Phase 1: scores ----
    for (int c = 0; c < nchunks; c++) {
        __syncthreads();
        // K chunk transposed: KVs[d][j] = K[s0+c*64+j][h*64+d], pitch 73
#pragma unroll
        for (int t = 0; t < 4; t++) {
            int gi = tid + t * 256;
            int j = gi >> 4;
            int d4 = (gi & 15) * 4;
            int krow = s0 + c * 64 + j;
            float4 kv = make_float4(0.f, 0.f, 0.f, 0.f);
            if (krow < s1) {
                kv = *(const float4*)(k + (size_t)krow * DMODEL + h * HDIM + d4);
            }
            KVs[(d4 + 0) * KVPITCH_K + j] = kv.x;
            KVs[(d4 + 1) * KVPITCH_K + j] = kv.y;
            KVs[(d4 + 2) * KVPITCH_K + j] = kv.z;
            KVs[(d4 + 3) * KVPITCH_K + j] = kv.w;
        }
        __syncthreads();

        float acc[4][4];
#pragma unroll
        for (int nt = 0; nt < 4; nt++) {
#pragma unroll
            for (int e = 0; e < 4; e++) acc[nt][e] = 0.f;
        }
#pragma unroll
        for (int ks = 0; ks < 8; ks++) {
            int k0 = ks * 8;
#pragma unroll
            for (int nt = 0; nt < 4; nt++) {
                int n0 = wn * 32 + nt * 8;
                u32 b0 = __float_as_uint(KVs[(k0 + tig) * KVPITCH_K + n0 + gID]);
                u32 b1 = __float_as_uint(KVs[(k0 + 4 + tig) * KVPITCH_K + n0 + gID]);
                mma_tf32(acc[nt], qa[ks][0], qa[ks][1], qa[ks][2], qa[ks][3], b0, b1);
            }
        }
        int row0 = m0 + gID;
#pragma unroll
        for (int nt = 0; nt < 4; nt++) {
            int col = c * 64 + wn * 32 + nt * 8 + tig * 2;
            sc[row0 * SPITCH + col]           = acc[nt][0] * scale;
            sc[row0 * SPITCH + col + 1]       = acc[nt][1] * scale;
            sc[(row0 + 8) * SPITCH + col]     = acc[nt][2] * scale;
            sc[(row0 + 8) * SPITCH + col + 1] = acc[nt][3] * scale;
        }
    }
    __syncthreads();

    // ---- Phase 2: softmax (8 warps, 8 rows each), round P to tf32 ----
    for (int r = warp; r < 64; r += 8) {
        float* row = sc + r * SPITCH;
        float m = -FLT_MAX;
        for (int j = lane; j < len; j += 32) m = fmaxf(m, row[j]);
        for (int off = 16; off > 0; off >>= 1) {
            m = fmaxf(m, __shfl_xor_sync(0xffffffff, m, off));
        }
        float s = 0.f;
        for (int j = lane; j < len; j += 32) {
            float e = __expf(row[j] - m);
            row[j] = e;
            s += e;
        }
        for (int off = 16; off > 0; off >>= 1) {
            s += __shfl_xor_sync(0xffffffff, s, off);
        }
        float inv = 1.0f / s;
        for (int j = lane; j < len; j += 32) row[j] = to_tf32(row[j] * inv);
    }
    __syncthreads();

    // ---- Phase 3: O = P @ V ----
    float acco[4][4];
#pragma unroll
    for (int nt = 0; nt < 4; nt++) {
#pragma unroll
        for (int e = 0; e < 4; e++) acco[nt][e] = 0.f;
    }

    for (int c = 0; c < nchunks; c++) {
        __syncthreads();
        // V chunk natural: KVs[j][d], pitch 72
#pragma unroll
        for (int t = 0; t < 4; t++) {
            int gi = tid + t * 256;
            int j = gi >> 4;
            int d4 = (gi & 15) * 4;
            int vrow = s0 + c * 64 + j;
            float4 vv = make_float4(0.f, 0.f, 0.f, 0.f);
            if (vrow < s1) {
                vv = *(const float4*)(v + (size_t)vrow * DMODEL + h * HDIM + d4);
            }
            *(float4*)(KVs + j * KVPITCH_V + d4) = vv;
        }
        __syncthreads();

#pragma unroll
        for (int ks = 0; ks < 8; ks++) {
            int kg = c * 64 + ks * 8;   // global key offset for P columns
            int kl = ks * 8;            // local key offset for V rows
            u32 pa0 = __float_as_uint(sc[(m0 + gID) * SPITCH + kg + tig]);
            u32 pa1 = __float_as_uint(sc[(m0 + 8 + gID) * SPITCH + kg + tig]);
            u32 pa2 = __float_as_uint(sc[(m0 + gID) * SPITCH + kg + 4 + tig]);
            u32 pa3 = __float_as_uint(sc[(m0 + 8 + gID) * SPITCH + kg + 4 + tig]);
#pragma unroll
            for (int nt = 0; nt < 4; nt++) {
                int n0 = wn * 32 + nt * 8;
                u32 b0 = __float_as_uint(KVs[(kl + tig) * KVPITCH_V + n0 + gID]);
                u32 b1 = __float_as_uint(KVs[(kl + 4 + tig) * KVPITCH_V + n0 + gID]);
                mma_tf32(acco[nt], pa0, pa1, pa2, pa3, b0, b1);
            }
        }
    }

    // ---- epilogue: write tf32-rounded attention output ----
    int orow0 = q0 + m0 + gID;
#pragma unroll
    for (int nt = 0; nt < 4; nt++) {
        int col = h * HDIM + wn * 32 + nt * 8 + tig * 2;
        outp[(size_t)orow0 * DMODEL + col]           = to_tf32(acco[nt][0]);
        outp[(size_t)orow0 * DMODEL + col + 1]       = to_tf32(acco[nt][1]);
        outp[(size_t)(orow0 + 8) * DMODEL + col]     = to_tf32(acco[nt][2]);
        outp[(size_t)(orow0 + 8) * DMODEL + col + 1] = to_tf32(acco[nt][3]);
    }
}

// ---------------------------------------------------------------------------
// launch
// ---------------------------------------------------------------------------
extern "C" void kernel_launch(void* const* d_in, const int* in_sizes, int n_in,
                              void* d_out, int out_size) {
    const float* hidden = (const float*)d_in[0];
    const int*   cu     = (const int*)d_in[1];
    const float* Wq = (const float*)d_in[2];
    const float* bq = (const float*)d_in[3];
    const float* Wk = (const float*)d_in[4];
    const float* Wv = (const float*)d_in[5];
    const float* bv = (const float*)d_in[6];
    const float* Wo = (const float*)d_in[7];
    const float* bo = (const float*)d_in[8];
    const float* ln1_g = (const float*)d_in[9];
    const float* ln1_b = (const float*)d_in[10];
    const float* Wf1 = (const float*)d_in[11];
    const float* bf1 = (const float*)d_in[12];
    const float* Wf2 = (const float*)d_in[13];
    const float* bf2 = (const float*)d_in[14];
    const float* ln2_g = (const float*)d_in[15];
    const float* ln2_b = (const float*)d_in[16];
    float* out = (float*)d_out;

    float *qp, *kp, *vp, *hp, *xlnp, *attnp, *ylnp, *ffnp;
    float *wqp, *wkp, *wvp, *wop, *wf1p, *wf2p;
    cudaGetSymbolAddress((void**)&qp,   g_q);
    cudaGetSymbolAddress((void**)&kp,   g_k);
    cudaGetSymbolAddress((void**)&vp,   g_v);
    cudaGetSymbolAddress((void**)&hp,   g_h);
    cudaGetSymbolAddress((void**)&xlnp, g_xln);
    cudaGetSymbolAddress((void**)&attnp,g_attn);
    cudaGetSymbolAddress((void**)&ylnp, g_yln);
    cudaGetSymbolAddress((void**)&ffnp, g_ffn);
    cudaGetSymbolAddress((void**)&wqp,  g_wq);
    cudaGetSymbolAddress((void**)&wkp,  g_wk);
    cudaGetSymbolAddress((void**)&wvp,  g_wv);
    cudaGetSymbolAddress((void**)&wop,  g_wo);
    cudaGetSymbolAddress((void**)&wf1p, g_wf1);
    cudaGetSymbolAddress((void**)&wf2p, g_wf2);

    static bool attr_set = false;
    if (!attr_set) {
        cudaFuncSetAttribute(attn_kernel, cudaFuncAttributeMaxDynamicSharedMemorySize,
                             ATT_SMEM_FLOATS * (int)sizeof(float));
        attr_set = true;
    }

    dim3 blk(256);
    int nDD4 = DMODEL * DMODEL / 4;
    int nDF4 = DMODEL * FFN / 4;
    cvt_kernel<<<(nDD4 + 255) / 256, blk>>>(Wq,  wqp,  nDD4);
    cvt_kernel<<<(nDD4 + 255) / 256, blk>>>(Wk,  wkp,  nDD4);
    cvt_kernel<<<(nDD4 + 255) / 256, blk>>>(Wv,  wvp,  nDD4);
    cvt_kernel<<<(nDD4 + 255) / 256, blk>>>(Wo,  wop,  nDD4);
    cvt_kernel<<<(nDF4 + 255) / 256, blk>>>(Wf1, wf1p, nDF4);
    cvt_kernel<<<(nDF4 + 255) / 256, blk>>>(Wf2, wf2p, nDF4);

    dim3 gemmDD(DMODEL / 128, SEQ / 128);
    dim3 gemmDF(FFN / 128, SEQ / 128);

    ln_kernel<<<SEQ, blk>>>(hidden, ln1_g, ln1_b, xlnp);
    // QKV outputs tf32-rounded (attention mma operands)
    tgemm_kernel<EPI_BIAS, 1><<<gemmDD, blk>>>(xlnp, wqp, bq, 0, qp, SEQ, DMODEL, DMODEL);
    tgemm_kernel<EPI_BIAS, 1><<<gemmDD, blk>>>(xlnp, wkp, 0, 0, kp, SEQ, DMODEL, DMODEL);
    tgemm_kernel<EPI_BIAS, 1><<<gemmDD, blk>>>(xlnp, wvp, bv, 0, vp, SEQ, DMODEL, DMODEL);
    attn_kernel<<<dim3(SEQ / 64, NHEAD), blk, ATT_SMEM_FLOATS * sizeof(float)>>>(
        qp, kp, vp, cu, attnp);
    tgemm_kernel<EPI_RES, 0><<<gemmDD, blk>>>(attnp, wop, bo, hidden, hp,
                                              SEQ, DMODEL, DMODEL);
    ln_kernel<<<SEQ, blk>>>(hp, ln2_g, ln2_b, ylnp);
    tgemm_kernel<EPI_GELU, 1><<<gemmDF, blk>>>(ylnp, wf1p, bf1, 0, ffnp,
                                               SEQ, FFN, DMODEL);
    tgemm_kernel<EPI_RES, 0><<<gemmDD, blk>>>(ffnp, wf2p, bf2, hp, out,
                                              SEQ, DMODEL, FFN);
}